// round 13
// baseline (speedup 1.0000x reference)
#include <cuda_runtime.h>
#include <cuda_fp16.h>
#include <math.h>
#include <stdint.h>

// Problem constants
#define BQ   16
#define NP   2048
#define DF   256
#define NH   8
#define DHD  64
#define KN   8
#define ID   512
#define QKV3 1536
#define RAD2 0.09f
#define LNEPS 1e-5f

// Scratch (static device globals; runtime allocation is forbidden)
__device__ int    g_idx[BQ * NP * KN];
__device__ __half g_normed_h[BQ * NP * DF];
__device__ __half g_qkv_h[BQ * NP * QKV3];
__device__ __half g_ao_h[BQ * NP * ID];
__device__ __half g_wqkv_h[DF * QKV3];
__device__ __half g_wout_h[ID * DF];

// ---------------------------------------------------------------------------
// PTX helpers
// ---------------------------------------------------------------------------
__device__ __forceinline__ void mma_f16(float* c, const uint32_t* a, const uint32_t* b) {
    asm volatile(
        "mma.sync.aligned.m16n8k16.row.col.f32.f16.f16.f32 "
        "{%0,%1,%2,%3}, {%4,%5,%6,%7}, {%8,%9}, {%0,%1,%2,%3};"
        : "+f"(c[0]), "+f"(c[1]), "+f"(c[2]), "+f"(c[3])
        : "r"(a[0]), "r"(a[1]), "r"(a[2]), "r"(a[3]), "r"(b[0]), "r"(b[1]));
}
__device__ __forceinline__ void ldsm_x4(uint32_t& r0, uint32_t& r1, uint32_t& r2,
                                        uint32_t& r3, uint32_t addr) {
    asm volatile("ldmatrix.sync.aligned.m8n8.x4.shared.b16 {%0,%1,%2,%3}, [%4];"
                 : "=r"(r0), "=r"(r1), "=r"(r2), "=r"(r3) : "r"(addr));
}
__device__ __forceinline__ void ldsm_x4t(uint32_t& r0, uint32_t& r1, uint32_t& r2,
                                         uint32_t& r3, uint32_t addr) {
    asm volatile("ldmatrix.sync.aligned.m8n8.x4.trans.shared.b16 {%0,%1,%2,%3}, [%4];"
                 : "=r"(r0), "=r"(r1), "=r"(r2), "=r"(r3) : "r"(addr));
}
__device__ __forceinline__ void cp16(uint32_t smem_dst, const void* gsrc) {
    asm volatile("cp.async.cg.shared.global [%0], [%1], 16;" :: "r"(smem_dst), "l"(gsrc));
}
__device__ __forceinline__ void cp_commit() { asm volatile("cp.async.commit_group;"); }
template <int N>
__device__ __forceinline__ void cp_wait() { asm volatile("cp.async.wait_group %0;" :: "n"(N)); }
__device__ __forceinline__ uint32_t smem_u32(const void* p) {
    return (uint32_t)__cvta_generic_to_shared(p);
}

// ---------------------------------------------------------------------------
// Kernel 1 "prep": LN (blocks 0..4095), w_qkv conv (..4479), w_out conv
// (..4607). Zero shared memory -> full occupancy.
// ---------------------------------------------------------------------------
#define LN_BLOCKS 4096
#define CV1_BLOCKS 384
#define CV2_BLOCKS 128
#define PREP_BLOCKS (LN_BLOCKS + CV1_BLOCKS + CV2_BLOCKS)

__global__ void __launch_bounds__(256) prep_kernel(
    const float* __restrict__ feature, const float* __restrict__ gam,
    const float* __restrict__ bet, const float* __restrict__ w_qkv,
    const float* __restrict__ w_out) {
    const int bid = blockIdx.x;
    const int tid = threadIdx.x;
    if (bid < LN_BLOCKS) {
        const int row = bid * 8 + (tid >> 5);
        const int lane = tid & 31;
        const float* f = feature + (size_t)row * DF + lane * 8;
        float v[8];
        float4 v0 = *(const float4*)f;
        float4 v1 = *(const float4*)(f + 4);
        v[0] = v0.x; v[1] = v0.y; v[2] = v0.z; v[3] = v0.w;
        v[4] = v1.x; v[5] = v1.y; v[6] = v1.z; v[7] = v1.w;
        float s = 0.f;
#pragma unroll
        for (int i = 0; i < 8; i++) s += v[i];
#pragma unroll
        for (int o = 16; o; o >>= 1) s += __shfl_xor_sync(0xffffffffu, s, o);
        const float mu = s * (1.0f / DF);
        float sq = 0.f;
#pragma unroll
        for (int i = 0; i < 8; i++) { float d = v[i] - mu; sq += d * d; }
#pragma unroll
        for (int o = 16; o; o >>= 1) sq += __shfl_xor_sync(0xffffffffu, sq, o);
        const float rs = rsqrtf(sq * (1.0f / DF) + LNEPS);
        const float* gp = gam + lane * 8;
        const float* bp = bet + lane * 8;
        __half2 o[4];
#pragma unroll
        for (int i = 0; i < 4; i++) {
            float a = (v[2 * i] - mu) * rs * gp[2 * i] + bp[2 * i];
            float c = (v[2 * i + 1] - mu) * rs * gp[2 * i + 1] + bp[2 * i + 1];
            o[i] = __floats2half2_rn(a, c);
        }
        __half2* op = (__half2*)(g_normed_h + (size_t)row * DF + lane * 8);
#pragma unroll
        for (int i = 0; i < 4; i++) op[i] = o[i];
    } else if (bid < LN_BLOCKS + CV1_BLOCKS) {
        const int i = ((bid - LN_BLOCKS) * 256 + tid) * 4;
        float4 v = *(const float4*)(w_qkv + i);
        __half2* d = (__half2*)(g_wqkv_h + i);
        d[0] = __floats2half2_rn(v.x, v.y);
        d[1] = __floats2half2_rn(v.z, v.w);
    } else {
        const int i = ((bid - LN_BLOCKS - CV1_BLOCKS) * 256 + tid) * 4;
        float4 v = *(const float4*)(w_out + i);
        __half2* d = (__half2*)(g_wout_h + i);
        d[0] = __floats2half2_rn(v.x, v.y);
        d[1] = __floats2half2_rn(v.z, v.w);
    }
}

// ---------------------------------------------------------------------------
// GEMM core: k-tile 64, 3-stage cp.async pipeline, compile-time N/K, full
// unroll. 128x128 block tile, 8 warps (4x2), warp tile 32x64, m16n8k16.
//   As: [128][72] halves (stride 36 words = 4 mod 32 -> conflict-free ldsm)
//   Bs: [64][136] halves (stride 68 words = 4 mod 32 -> conflict-free)
// ---------------------------------------------------------------------------
#define ASH 72
#define BSH 136
#define STG 3
#define A_STAGE_H (128 * ASH)
#define B_STAGE_H (64 * BSH)
#define GEMM_SMEM ((STG * (A_STAGE_H + B_STAGE_H)) * 2)   /* 107520 B */

template <int EPI, int Nc, int Kc>
__device__ __forceinline__ void gemm_body(
    __half* sh, int brow, int bcol,
    const __half* __restrict__ A, const __half* __restrict__ Bm, void* __restrict__ Cv,
    const float* __restrict__ bias, const float* __restrict__ resid) {
    __half* AsBase = sh;
    __half* BsBase = sh + STG * A_STAGE_H;
    constexpr int KT = Kc / 64;

    const int tid = threadIdx.x;
    const int warp = tid >> 5, lane = tid & 31;
    const int warp_m = warp >> 1, warp_n = warp & 1;

    // A copy: thread -> row tid>>1, half-base (tid&1)*32, 4 chunks of 8 halves
    const int a_r0 = tid >> 1;
    const int a_c0 = (tid & 1) * 32;
    // B copy: thread -> row tid>>2, chunk base (tid&3)*4, 4 chunks
    const int b_r0 = tid >> 2;
    const int b_c0 = (tid & 3) * 32;

    auto load_tile = [&](int kt, int buf) {
        const uint32_t as_base = smem_u32(AsBase + buf * A_STAGE_H);
        const uint32_t bs_base = smem_u32(BsBase + buf * B_STAGE_H);
#pragma unroll
        for (int i = 0; i < 4; i++) {
            const int c = a_c0 + i * 8;
            cp16(as_base + (a_r0 * ASH + c) * 2,
                 A + (size_t)(brow + a_r0) * Kc + kt * 64 + c);
        }
#pragma unroll
        for (int i = 0; i < 4; i++) {
            const int c = b_c0 + i * 8;
            cp16(bs_base + (b_r0 * BSH + c) * 2,
                 Bm + (size_t)(kt * 64 + b_r0) * Nc + bcol + c);
        }
        cp_commit();
    };

    float acc[2][8][4];
#pragma unroll
    for (int mt = 0; mt < 2; mt++)
#pragma unroll
        for (int nt = 0; nt < 8; nt++)
#pragma unroll
            for (int r = 0; r < 4; r++) acc[mt][nt][r] = 0.f;

    load_tile(0, 0);
    load_tile(1, 1);

    const int lg = lane >> 2;
    const int lt = lane & 3;
    const int a_lrow = (lane & 15);
    const int a_lcol = ((lane >> 4) << 3);
    const int b_lk = (lane & 7) + ((lane >> 3) & 1) * 8;
    const int b_ln = ((lane >> 4) << 3);

#pragma unroll
    for (int kt = 0; kt < KT; kt++) {
        const int buf = kt % STG;
        cp_wait<STG - 2>();
        __syncthreads();

        const uint32_t as_u = smem_u32(AsBase + buf * A_STAGE_H);
        const uint32_t bs_u = smem_u32(BsBase + buf * B_STAGE_H);
#pragma unroll
        for (int ks = 0; ks < 4; ks++) {
            uint32_t af[2][4], bf[8][2];
#pragma unroll
            for (int mt = 0; mt < 2; mt++) {
                const int row = warp_m * 32 + mt * 16 + a_lrow;
                const int col = ks * 16 + a_lcol;
                ldsm_x4(af[mt][0], af[mt][1], af[mt][2], af[mt][3],
                        as_u + (row * ASH + col) * 2);
            }
#pragma unroll
            for (int np = 0; np < 4; np++) {
                const int k = ks * 16 + b_lk;
                const int n = warp_n * 64 + np * 16 + b_ln;
                ldsm_x4t(bf[2 * np][0], bf[2 * np][1], bf[2 * np + 1][0], bf[2 * np + 1][1],
                         bs_u + (k * BSH + n) * 2);
            }
#pragma unroll
            for (int mt = 0; mt < 2; mt++)
#pragma unroll
                for (int nt = 0; nt < 8; nt++)
                    mma_f16(acc[mt][nt], af[mt], bf[nt]);
        }

        if (kt + 2 < KT) load_tile(kt + 2, (kt + 2) % STG);
        else cp_commit();
    }

#pragma unroll
    for (int mt = 0; mt < 2; mt++) {
#pragma unroll
        for (int nt = 0; nt < 8; nt++) {
            const int r = brow + warp_m * 32 + mt * 16 + lg;
            const int c = bcol + warp_n * 64 + nt * 8 + 2 * lt;
#pragma unroll
            for (int h = 0; h < 2; h++) {
                const int rr = r + h * 8;
                float x0 = acc[mt][nt][h * 2 + 0];
                float x1 = acc[mt][nt][h * 2 + 1];
                if (EPI == 0) {
                    __half* C = (__half*)Cv;
                    *(__half2*)(C + (size_t)rr * Nc + c) = __floats2half2_rn(x0, x1);
                } else {
                    float* C = (float*)Cv;
                    const float* rp = resid + (size_t)rr * Nc + c;
                    float a0 = x0 + bias[c];
                    float a1 = x1 + bias[c + 1];
                    float g0 = 0.5f * a0 * (1.0f + erff(a0 * 0.70710678118654752f));
                    float g1 = 0.5f * a1 * (1.0f + erff(a1 * 0.70710678118654752f));
                    float2 o = {g0 + rp[0], g1 + rp[1]};
                    *(float2*)(C + (size_t)rr * Nc + c) = o;
                }
            }
        }
    }
}

// ---------------------------------------------------------------------------
// Kernel: fused ball_query (blocks 0..127) + qkv GEMM (blocks 128..3199).
// ---------------------------------------------------------------------------
#define BALL_BLOCKS 128
#define QKV_TILES_X (QKV3 / 128)   /* 12 */

__global__ void __launch_bounds__(256) ballqkv_kernel(
    const float* __restrict__ xyzs, const __half* __restrict__ A,
    const __half* __restrict__ Bm, __half* __restrict__ C) {
    extern __shared__ char smem_raw[];
    const int tid = threadIdx.x;

    if (blockIdx.x < BALL_BLOCKS) {
        float4* sp = (float4*)smem_raw;
        const int b = blockIdx.x >> 3;
        const int n = ((blockIdx.x & 7) << 8) + tid;
        const float* xb = xyzs + (size_t)b * NP * 3;
        for (int m = tid; m < NP; m += 256) {
            float x = xb[3 * m], y = xb[3 * m + 1], z = xb[3 * m + 2];
            sp[m] = make_float4(x, y, z, x * x + y * y + z * z);
        }
        __syncthreads();
        const float4 q = sp[n];
        int i0 = 0, i1 = 0, i2 = 0, i3 = 0, i4 = 0, i5 = 0, i6 = 0, i7 = 0;
        int cnt = 0;
#pragma unroll 4
        for (int m = 0; m < NP; m++) {
            const float4 c = sp[m];
            const float d2 = q.w + c.w - 2.0f * (q.x * c.x + q.y * c.y + q.z * c.z);
            if (d2 < RAD2 && cnt < KN) {
                if      (cnt == 0) i0 = m;
                else if (cnt == 1) i1 = m;
                else if (cnt == 2) i2 = m;
                else if (cnt == 3) i3 = m;
                else if (cnt == 4) i4 = m;
                else if (cnt == 5) i5 = m;
                else if (cnt == 6) i6 = m;
                else               i7 = m;
                cnt++;
            }
        }
        int* op = g_idx + ((size_t)b * NP + n) * KN;
        op[0] = i0;
        op[1] = (cnt > 1) ? i1 : i0;
        op[2] = (cnt > 2) ? i2 : i0;
        op[3] = (cnt > 3) ? i3 : i0;
        op[4] = (cnt > 4) ? i4 : i0;
        op[5] = (cnt > 5) ? i5 : i0;
        op[6] = (cnt > 6) ? i6 : i0;
        op[7] = (cnt > 7) ? i7 : i0;
        return;
    }

    const int t = blockIdx.x - BALL_BLOCKS;
    const int bcol = (t % QKV_TILES_X) * 128;
    const int brow = (t / QKV_TILES_X) * 128;
    gemm_body<0, QKV3, DF>((__half*)smem_raw, brow, bcol, A, Bm, C, nullptr, nullptr);
}

// ---------------------------------------------------------------------------
// Kernel: out GEMM + bias + exact GELU + residual (templated dims).
// ---------------------------------------------------------------------------
__global__ void __launch_bounds__(256) out_gemm_kernel(
    const __half* __restrict__ A, const __half* __restrict__ Bm, float* __restrict__ C,
    const float* __restrict__ bias, const float* __restrict__ resid) {
    extern __shared__ char smem_raw[];
    const int bcol = blockIdx.x * 128;
    const int brow = blockIdx.y * 128;
    gemm_body<1, DF, ID>((__half*)smem_raw, brow, bcol, A, Bm, C, bias, resid);
}

// ---------------------------------------------------------------------------
// Kernel: attention v2. 8-lane groups: lane owns 8 dims of one head.
// ---------------------------------------------------------------------------
__global__ void __launch_bounds__(256) attn_kernel(const float* __restrict__ xyzs,
                                                   const float* __restrict__ w_sp) {
    const int warp = threadIdx.x >> 5;
    const int lane = threadIdx.x & 31;
    const int p = blockIdx.x * 4 + (warp >> 1);
    const int b = p >> 11;
    const int head = ((warp & 1) << 2) + (lane >> 3);
    const int r = lane & 7;

    int my_idx = 0;
    float dx = 0.f, dy = 0.f, dz = 0.f;
    if (lane < KN) {
        my_idx = __ldg(&g_idx[(size_t)p * KN + lane]);
        const float* xn = xyzs + ((size_t)b * NP + my_idx) * 3;
        const float* xq = xyzs + (size_t)p * 3;
        dx = xn[0] - xq[0];
        dy = xn[1] - xq[1];
        dz = xn[2] - xq[2];
    }
    int idxs[KN];
#pragma unroll
    for (int j = 0; j < KN; j++) idxs[j] = __shfl_sync(0xffffffffu, my_idx, j);

    const size_t rowoff = (size_t)head * DHD + r * 8;
    uint4 qu = *(const uint4*)(g_qkv_h + (size_t)p * QKV3 + rowoff);
    float2 qf[4];
    {
        const __half2* qh = (const __half2*)&qu;
#pragma unroll
        for (int i = 0; i < 4; i++) qf[i] = __half22float2(qh[i]);
    }

    uint4 ku[KN];
#pragma unroll
    for (int j = 0; j < KN; j++)
        ku[j] = *(const uint4*)(g_qkv_h + ((size_t)b * NP + idxs[j]) * QKV3 + ID + rowoff);
    float logits[KN];
#pragma unroll
    for (int j = 0; j < KN; j++) {
        const __half2* kh = (const __half2*)&ku[j];
        float d = 0.f;
#pragma unroll
        for (int i = 0; i < 4; i++) {
            float2 kf = __half22float2(kh[i]);
            d = fmaf(qf[i].x, kf.x, d);
            d = fmaf(qf[i].y, kf.y, d);
        }
        d += __shfl_xor_sync(0xffffffffu, d, 1);
        d += __shfl_xor_sync(0xffffffffu, d, 2);
        d += __shfl_xor_sync(0xffffffffu, d, 4);
        logits[j] = d * 0.125f;
    }

    float mx = logits[0];
#pragma unroll
    for (int j = 1; j < KN; j++) mx = fmaxf(mx, logits[j]);
    float a[KN];
    float se = 0.f;
#pragma unroll
    for (int j = 0; j < KN; j++) { a[j] = __expf(logits[j] - mx); se += a[j]; }
    const float inv = 1.0f / se;
#pragma unroll
    for (int j = 0; j < KN; j++) a[j] *= inv;

    uint4 vu[KN];
#pragma unroll
    for (int j = 0; j < KN; j++)
        vu[j] = *(const uint4*)(g_qkv_h + ((size_t)b * NP + idxs[j]) * QKV3 + 2 * ID + rowoff);
    float ov[8];
#pragma unroll
    for (int i = 0; i < 8; i++) ov[i] = 0.f;
#pragma unroll
    for (int j = 0; j < KN; j++) {
        const __half2* vh = (const __half2*)&vu[j];
#pragma unroll
        for (int i = 0; i < 4; i++) {
            float2 vf = __half22float2(vh[i]);
            ov[2 * i]     = fmaf(a[j], vf.x, ov[2 * i]);
            ov[2 * i + 1] = fmaf(a[j], vf.y, ov[2 * i + 1]);
        }
    }

    float dm[3];
#pragma unroll
    for (int cc = 0; cc < 3; cc++) {
        float m = -1e30f;
#pragma unroll
        for (int j = 0; j < KN; j++) {
            float dj = __shfl_sync(0xffffffffu, cc == 0 ? dx : (cc == 1 ? dy : dz), j);
            m = fmaxf(m, a[j] * dj);
        }
        dm[cc] = m;
    }

    uint4 ou;
    __half2* oh = (__half2*)&ou;
#pragma unroll
    for (int i = 0; i < 4; i++) {
        const int d0 = r * 8 + 2 * i;
        const int d1 = d0 + 1;
        float s0 = ov[2 * i] + dm[0] * w_sp[d0] + dm[1] * w_sp[64 + d0] + dm[2] * w_sp[128 + d0];
        float s1 = ov[2 * i + 1] + dm[0] * w_sp[d1] + dm[1] * w_sp[64 + d1] + dm[2] * w_sp[128 + d1];
        oh[i] = __floats2half2_rn(s0, s1);
    }
    *(uint4*)(g_ao_h + (size_t)p * ID + rowoff) = ou;
}

// ---------------------------------------------------------------------------
extern "C" void kernel_launch(void* const* d_in, const int* in_sizes, int n_in,
                              void* d_out, int out_size) {
    (void)in_sizes; (void)n_in; (void)out_size;
    const float* xyzs    = (const float*)d_in[0];
    const float* feature = (const float*)d_in[1];
    const float* ln_g    = (const float*)d_in[2];
    const float* ln_b    = (const float*)d_in[3];
    const float* w_qkv   = (const float*)d_in[4];
    const float* w_sp    = (const float*)d_in[5];
    const float* w_out   = (const float*)d_in[6];
    const float* b_out   = (const float*)d_in[7];
    float* out = (float*)d_out;

    void *p_normed, *p_qkv, *p_ao, *p_wqkv, *p_wout;
    cudaGetSymbolAddress(&p_normed, g_normed_h);
    cudaGetSymbolAddress(&p_qkv, g_qkv_h);
    cudaGetSymbolAddress(&p_ao, g_ao_h);
    cudaGetSymbolAddress(&p_wqkv, g_wqkv_h);
    cudaGetSymbolAddress(&p_wout, g_wout_h);
    __half* normed = (__half*)p_normed;
    __half* qkv = (__half*)p_qkv;
    __half* ao = (__half*)p_ao;
    __half* wqkv = (__half*)p_wqkv;
    __half* wout = (__half*)p_wout;

    cudaFuncSetAttribute(ballqkv_kernel, cudaFuncAttributeMaxDynamicSharedMemorySize,
                         GEMM_SMEM);
    cudaFuncSetAttribute(out_gemm_kernel, cudaFuncAttributeMaxDynamicSharedMemorySize,
                         GEMM_SMEM);

    // 1) prep: LN -> fp16 + weight conversions
    prep_kernel<<<PREP_BLOCKS, 256>>>(feature, ln_g, ln_b, w_qkv, w_out);
    // 2) ball query + qkv GEMM (independent; one launch)
    ballqkv_kernel<<<BALL_BLOCKS + QKV_TILES_X * ((BQ * NP) / 128), 256, GEMM_SMEM>>>(
        xyzs, normed, wqkv, qkv);
    // 3) attention + spatial op -> g_ao (fp16)
    attn_kernel<<<(BQ * NP) / 4, 256>>>(xyzs, w_sp);
    // 4) out = gelu(ao @ w_out + b_out) + feature -> fp32
    out_gemm_kernel<<<dim3(DF / 128, (BQ * NP) / 128), 256, GEMM_SMEM>>>(
        ao, wout, out, b_out, feature);
}

// round 14
// speedup vs baseline: 1.1333x; 1.1333x over previous
#include <cuda_runtime.h>
#include <cuda_fp16.h>
#include <math.h>
#include <stdint.h>

// Problem constants
#define BQ   16
#define NP   2048
#define DF   256
#define NH   8
#define DHD  64
#define KN   8
#define ID   512
#define QKV3 1536
#define RAD2 0.09f
#define LNEPS 1e-5f

// Scratch (static device globals; runtime allocation is forbidden)
__device__ int    g_idx[BQ * NP * KN];
__device__ __half g_normed_h[BQ * NP * DF];
__device__ __half g_qkv_h[BQ * NP * QKV3];
__device__ __half g_ao_h[BQ * NP * ID];
__device__ __half g_wqkv_h[DF * QKV3];
__device__ __half g_wout_h[ID * DF];

// ---------------------------------------------------------------------------
// PTX helpers
// ---------------------------------------------------------------------------
__device__ __forceinline__ void mma_f16(float* c, const uint32_t* a, const uint32_t* b) {
    asm volatile(
        "mma.sync.aligned.m16n8k16.row.col.f32.f16.f16.f32 "
        "{%0,%1,%2,%3}, {%4,%5,%6,%7}, {%8,%9}, {%0,%1,%2,%3};"
        : "+f"(c[0]), "+f"(c[1]), "+f"(c[2]), "+f"(c[3])
        : "r"(a[0]), "r"(a[1]), "r"(a[2]), "r"(a[3]), "r"(b[0]), "r"(b[1]));
}
__device__ __forceinline__ void ldsm_x4(uint32_t& r0, uint32_t& r1, uint32_t& r2,
                                        uint32_t& r3, uint32_t addr) {
    asm volatile("ldmatrix.sync.aligned.m8n8.x4.shared.b16 {%0,%1,%2,%3}, [%4];"
                 : "=r"(r0), "=r"(r1), "=r"(r2), "=r"(r3) : "r"(addr));
}
__device__ __forceinline__ void ldsm_x4t(uint32_t& r0, uint32_t& r1, uint32_t& r2,
                                         uint32_t& r3, uint32_t addr) {
    asm volatile("ldmatrix.sync.aligned.m8n8.x4.trans.shared.b16 {%0,%1,%2,%3}, [%4];"
                 : "=r"(r0), "=r"(r1), "=r"(r2), "=r"(r3) : "r"(addr));
}
__device__ __forceinline__ void cp16(uint32_t smem_dst, const void* gsrc) {
    asm volatile("cp.async.cg.shared.global [%0], [%1], 16;" :: "r"(smem_dst), "l"(gsrc));
}
__device__ __forceinline__ void cp_commit() { asm volatile("cp.async.commit_group;"); }
template <int N>
__device__ __forceinline__ void cp_wait() { asm volatile("cp.async.wait_group %0;" :: "n"(N)); }
__device__ __forceinline__ uint32_t smem_u32(const void* p) {
    return (uint32_t)__cvta_generic_to_shared(p);
}

// ---------------------------------------------------------------------------
// Kernel 1 "prep": LN (blocks 0..4095), w_qkv conv (..4479), w_out conv
// (..4607). Zero shared memory -> full occupancy.
// ---------------------------------------------------------------------------
#define LN_BLOCKS 4096
#define CV1_BLOCKS 384
#define CV2_BLOCKS 128
#define PREP_BLOCKS (LN_BLOCKS + CV1_BLOCKS + CV2_BLOCKS)

__global__ void __launch_bounds__(256) prep_kernel(
    const float* __restrict__ feature, const float* __restrict__ gam,
    const float* __restrict__ bet, const float* __restrict__ w_qkv,
    const float* __restrict__ w_out) {
    const int bid = blockIdx.x;
    const int tid = threadIdx.x;
    if (bid < LN_BLOCKS) {
        const int row = bid * 8 + (tid >> 5);
        const int lane = tid & 31;
        const float* f = feature + (size_t)row * DF + lane * 8;
        float v[8];
        float4 v0 = *(const float4*)f;
        float4 v1 = *(const float4*)(f + 4);
        v[0] = v0.x; v[1] = v0.y; v[2] = v0.z; v[3] = v0.w;
        v[4] = v1.x; v[5] = v1.y; v[6] = v1.z; v[7] = v1.w;
        float s = 0.f;
#pragma unroll
        for (int i = 0; i < 8; i++) s += v[i];
#pragma unroll
        for (int o = 16; o; o >>= 1) s += __shfl_xor_sync(0xffffffffu, s, o);
        const float mu = s * (1.0f / DF);
        float sq = 0.f;
#pragma unroll
        for (int i = 0; i < 8; i++) { float d = v[i] - mu; sq += d * d; }
#pragma unroll
        for (int o = 16; o; o >>= 1) sq += __shfl_xor_sync(0xffffffffu, sq, o);
        const float rs = rsqrtf(sq * (1.0f / DF) + LNEPS);
        const float* gp = gam + lane * 8;
        const float* bp = bet + lane * 8;
        __half2 o[4];
#pragma unroll
        for (int i = 0; i < 4; i++) {
            float a = (v[2 * i] - mu) * rs * gp[2 * i] + bp[2 * i];
            float c = (v[2 * i + 1] - mu) * rs * gp[2 * i + 1] + bp[2 * i + 1];
            o[i] = __floats2half2_rn(a, c);
        }
        __half2* op = (__half2*)(g_normed_h + (size_t)row * DF + lane * 8);
#pragma unroll
        for (int i = 0; i < 4; i++) op[i] = o[i];
    } else if (bid < LN_BLOCKS + CV1_BLOCKS) {
        const int i = ((bid - LN_BLOCKS) * 256 + tid) * 4;
        float4 v = *(const float4*)(w_qkv + i);
        __half2* d = (__half2*)(g_wqkv_h + i);
        d[0] = __floats2half2_rn(v.x, v.y);
        d[1] = __floats2half2_rn(v.z, v.w);
    } else {
        const int i = ((bid - LN_BLOCKS - CV1_BLOCKS) * 256 + tid) * 4;
        float4 v = *(const float4*)(w_out + i);
        __half2* d = (__half2*)(g_wout_h + i);
        d[0] = __floats2half2_rn(v.x, v.y);
        d[1] = __floats2half2_rn(v.z, v.w);
    }
}

// ---------------------------------------------------------------------------
// GEMM core: k-tile 32, 4-stage cp.async pipeline, compile-time N/K,
// NON-unrolled kt mainloop (keeps the body L0-I$-resident).
// 128x128 block tile, 8 warps (4x2), warp tile 32x64, m16n8k16.
// ---------------------------------------------------------------------------
#define ASH 40
#define BSH 136
#define STG 4
#define A_STAGE_H (128 * ASH)
#define B_STAGE_H (32 * BSH)
#define GEMM_SMEM ((STG * (A_STAGE_H + B_STAGE_H)) * 2)   /* 75776 B */

template <int EPI, int Nc, int Kc>
__device__ __forceinline__ void gemm_body(
    __half* sh, int brow, int bcol,
    const __half* __restrict__ A, const __half* __restrict__ Bm, void* __restrict__ Cv,
    const float* __restrict__ bias, const float* __restrict__ resid) {
    __half* AsBase = sh;
    __half* BsBase = sh + STG * A_STAGE_H;
    constexpr int KT = Kc / 32;

    const int tid = threadIdx.x;
    const int warp = tid >> 5, lane = tid & 31;
    const int warp_m = warp >> 1, warp_n = warp & 1;

    const int a_r0 = tid >> 2;
    const int a_c = (tid & 3) * 8;
    const int b_r0 = tid >> 4;
    const int b_c = (tid & 15) * 8;

    auto load_tile = [&](int kt, int buf) {
        const uint32_t as_base = smem_u32(AsBase + buf * A_STAGE_H);
        const uint32_t bs_base = smem_u32(BsBase + buf * B_STAGE_H);
#pragma unroll
        for (int i = 0; i < 2; i++) {
            const int row = a_r0 + 64 * i;
            cp16(as_base + (row * ASH + a_c) * 2,
                 A + (size_t)(brow + row) * Kc + kt * 32 + a_c);
        }
#pragma unroll
        for (int i = 0; i < 2; i++) {
            const int row = b_r0 + 16 * i;
            cp16(bs_base + (row * BSH + b_c) * 2,
                 Bm + (size_t)(kt * 32 + row) * Nc + bcol + b_c);
        }
        cp_commit();
    };

    float acc[2][8][4];
#pragma unroll
    for (int mt = 0; mt < 2; mt++)
#pragma unroll
        for (int nt = 0; nt < 8; nt++)
#pragma unroll
            for (int r = 0; r < 4; r++) acc[mt][nt][r] = 0.f;

    load_tile(0, 0);
    load_tile(1, 1);
    load_tile(2, 2);

    const int lg = lane >> 2;
    const int lt = lane & 3;
    const int a_lrow = (lane & 15);
    const int a_lcol = ((lane >> 4) << 3);
    const int b_lk = (lane & 7) + ((lane >> 3) & 1) * 8;
    const int b_ln = ((lane >> 4) << 3);

#pragma unroll 1
    for (int kt = 0; kt < KT; kt++) {
        const int buf = kt & (STG - 1);
        cp_wait<STG - 2>();
        __syncthreads();

        const uint32_t as_u = smem_u32(AsBase + buf * A_STAGE_H);
        const uint32_t bs_u = smem_u32(BsBase + buf * B_STAGE_H);
#pragma unroll
        for (int ks = 0; ks < 2; ks++) {
            uint32_t af[2][4], bf[8][2];
#pragma unroll
            for (int mt = 0; mt < 2; mt++) {
                const int row = warp_m * 32 + mt * 16 + a_lrow;
                const int col = ks * 16 + a_lcol;
                ldsm_x4(af[mt][0], af[mt][1], af[mt][2], af[mt][3],
                        as_u + (row * ASH + col) * 2);
            }
#pragma unroll
            for (int np = 0; np < 4; np++) {
                const int k = ks * 16 + b_lk;
                const int n = warp_n * 64 + np * 16 + b_ln;
                ldsm_x4t(bf[2 * np][0], bf[2 * np][1], bf[2 * np + 1][0], bf[2 * np + 1][1],
                         bs_u + (k * BSH + n) * 2);
            }
#pragma unroll
            for (int mt = 0; mt < 2; mt++)
#pragma unroll
                for (int nt = 0; nt < 8; nt++)
                    mma_f16(acc[mt][nt], af[mt], bf[nt]);
        }

        if (kt + 3 < KT) load_tile(kt + 3, (kt + 3) & (STG - 1));
        else cp_commit();
    }

#pragma unroll
    for (int mt = 0; mt < 2; mt++) {
#pragma unroll
        for (int nt = 0; nt < 8; nt++) {
            const int r = brow + warp_m * 32 + mt * 16 + lg;
            const int c = bcol + warp_n * 64 + nt * 8 + 2 * lt;
#pragma unroll
            for (int h = 0; h < 2; h++) {
                const int rr = r + h * 8;
                float x0 = acc[mt][nt][h * 2 + 0];
                float x1 = acc[mt][nt][h * 2 + 1];
                if (EPI == 0) {
                    __half* C = (__half*)Cv;
                    *(__half2*)(C + (size_t)rr * Nc + c) = __floats2half2_rn(x0, x1);
                } else {
                    float* C = (float*)Cv;
                    const float* rp = resid + (size_t)rr * Nc + c;
                    float a0 = x0 + bias[c];
                    float a1 = x1 + bias[c + 1];
                    float g0 = 0.5f * a0 * (1.0f + erff(a0 * 0.70710678118654752f));
                    float g1 = 0.5f * a1 * (1.0f + erff(a1 * 0.70710678118654752f));
                    float2 o = {g0 + rp[0], g1 + rp[1]};
                    *(float2*)(C + (size_t)rr * Nc + c) = o;
                }
            }
        }
    }
}

// ---------------------------------------------------------------------------
// Kernel: fused ball_query (blocks 0..127) + qkv GEMM (blocks 128..3199).
// ---------------------------------------------------------------------------
#define BALL_BLOCKS 128
#define QKV_TILES_X (QKV3 / 128)   /* 12 */

__global__ void __launch_bounds__(256) ballqkv_kernel(
    const float* __restrict__ xyzs, const __half* __restrict__ A,
    const __half* __restrict__ Bm, __half* __restrict__ C) {
    extern __shared__ char smem_raw[];
    const int tid = threadIdx.x;

    if (blockIdx.x < BALL_BLOCKS) {
        float4* sp = (float4*)smem_raw;
        const int b = blockIdx.x >> 3;
        const int n = ((blockIdx.x & 7) << 8) + tid;
        const float* xb = xyzs + (size_t)b * NP * 3;
        for (int m = tid; m < NP; m += 256) {
            float x = xb[3 * m], y = xb[3 * m + 1], z = xb[3 * m + 2];
            sp[m] = make_float4(x, y, z, x * x + y * y + z * z);
        }
        __syncthreads();
        const float4 q = sp[n];
        int i0 = 0, i1 = 0, i2 = 0, i3 = 0, i4 = 0, i5 = 0, i6 = 0, i7 = 0;
        int cnt = 0;
#pragma unroll 4
        for (int m = 0; m < NP; m++) {
            const float4 c = sp[m];
            const float d2 = q.w + c.w - 2.0f * (q.x * c.x + q.y * c.y + q.z * c.z);
            if (d2 < RAD2 && cnt < KN) {
                if      (cnt == 0) i0 = m;
                else if (cnt == 1) i1 = m;
                else if (cnt == 2) i2 = m;
                else if (cnt == 3) i3 = m;
                else if (cnt == 4) i4 = m;
                else if (cnt == 5) i5 = m;
                else if (cnt == 6) i6 = m;
                else               i7 = m;
                cnt++;
            }
        }
        int* op = g_idx + ((size_t)b * NP + n) * KN;
        op[0] = i0;
        op[1] = (cnt > 1) ? i1 : i0;
        op[2] = (cnt > 2) ? i2 : i0;
        op[3] = (cnt > 3) ? i3 : i0;
        op[4] = (cnt > 4) ? i4 : i0;
        op[5] = (cnt > 5) ? i5 : i0;
        op[6] = (cnt > 6) ? i6 : i0;
        op[7] = (cnt > 7) ? i7 : i0;
        return;
    }

    const int t = blockIdx.x - BALL_BLOCKS;
    const int bcol = (t % QKV_TILES_X) * 128;
    const int brow = (t / QKV_TILES_X) * 128;
    gemm_body<0, QKV3, DF>((__half*)smem_raw, brow, bcol, A, Bm, C, nullptr, nullptr);
}

// ---------------------------------------------------------------------------
// Kernel: out GEMM + bias + exact GELU + residual (templated dims).
// ---------------------------------------------------------------------------
__global__ void __launch_bounds__(256) out_gemm_kernel(
    const __half* __restrict__ A, const __half* __restrict__ Bm, float* __restrict__ C,
    const float* __restrict__ bias, const float* __restrict__ resid) {
    extern __shared__ char smem_raw[];
    const int bcol = blockIdx.x * 128;
    const int brow = blockIdx.y * 128;
    gemm_body<1, DF, ID>((__half*)smem_raw, brow, bcol, A, Bm, C, bias, resid);
}

// ---------------------------------------------------------------------------
// Kernel: attention v2. 8-lane groups: lane owns 8 dims of one head.
// ---------------------------------------------------------------------------
__global__ void __launch_bounds__(256) attn_kernel(const float* __restrict__ xyzs,
                                                   const float* __restrict__ w_sp) {
    const int warp = threadIdx.x >> 5;
    const int lane = threadIdx.x & 31;
    const int p = blockIdx.x * 4 + (warp >> 1);
    const int b = p >> 11;
    const int head = ((warp & 1) << 2) + (lane >> 3);
    const int r = lane & 7;

    int my_idx = 0;
    float dx = 0.f, dy = 0.f, dz = 0.f;
    if (lane < KN) {
        my_idx = __ldg(&g_idx[(size_t)p * KN + lane]);
        const float* xn = xyzs + ((size_t)b * NP + my_idx) * 3;
        const float* xq = xyzs + (size_t)p * 3;
        dx = xn[0] - xq[0];
        dy = xn[1] - xq[1];
        dz = xn[2] - xq[2];
    }
    int idxs[KN];
#pragma unroll
    for (int j = 0; j < KN; j++) idxs[j] = __shfl_sync(0xffffffffu, my_idx, j);

    const size_t rowoff = (size_t)head * DHD + r * 8;
    uint4 qu = *(const uint4*)(g_qkv_h + (size_t)p * QKV3 + rowoff);
    float2 qf[4];
    {
        const __half2* qh = (const __half2*)&qu;
#pragma unroll
        for (int i = 0; i < 4; i++) qf[i] = __half22float2(qh[i]);
    }

    uint4 ku[KN];
#pragma unroll
    for (int j = 0; j < KN; j++)
        ku[j] = *(const uint4*)(g_qkv_h + ((size_t)b * NP + idxs[j]) * QKV3 + ID + rowoff);
    float logits[KN];
#pragma unroll
    for (int j = 0; j < KN; j++) {
        const __half2* kh = (const __half2*)&ku[j];
        float d = 0.f;
#pragma unroll
        for (int i = 0; i < 4; i++) {
            float2 kf = __half22float2(kh[i]);
            d = fmaf(qf[i].x, kf.x, d);
            d = fmaf(qf[i].y, kf.y, d);
        }
        d += __shfl_xor_sync(0xffffffffu, d, 1);
        d += __shfl_xor_sync(0xffffffffu, d, 2);
        d += __shfl_xor_sync(0xffffffffu, d, 4);
        logits[j] = d * 0.125f;
    }

    float mx = logits[0];
#pragma unroll
    for (int j = 1; j < KN; j++) mx = fmaxf(mx, logits[j]);
    float a[KN];
    float se = 0.f;
#pragma unroll
    for (int j = 0; j < KN; j++) { a[j] = __expf(logits[j] - mx); se += a[j]; }
    const float inv = 1.0f / se;
#pragma unroll
    for (int j = 0; j < KN; j++) a[j] *= inv;

    uint4 vu[KN];
#pragma unroll
    for (int j = 0; j < KN; j++)
        vu[j] = *(const uint4*)(g_qkv_h + ((size_t)b * NP + idxs[j]) * QKV3 + 2 * ID + rowoff);
    float ov[8];
#pragma unroll
    for (int i = 0; i < 8; i++) ov[i] = 0.f;
#pragma unroll
    for (int j = 0; j < KN; j++) {
        const __half2* vh = (const __half2*)&vu[j];
#pragma unroll
        for (int i = 0; i < 4; i++) {
            float2 vf = __half22float2(vh[i]);
            ov[2 * i]     = fmaf(a[j], vf.x, ov[2 * i]);
            ov[2 * i + 1] = fmaf(a[j], vf.y, ov[2 * i + 1]);
        }
    }

    float dm[3];
#pragma unroll
    for (int cc = 0; cc < 3; cc++) {
        float m = -1e30f;
#pragma unroll
        for (int j = 0; j < KN; j++) {
            float dj = __shfl_sync(0xffffffffu, cc == 0 ? dx : (cc == 1 ? dy : dz), j);
            m = fmaxf(m, a[j] * dj);
        }
        dm[cc] = m;
    }

    uint4 ou;
    __half2* oh = (__half2*)&ou;
#pragma unroll
    for (int i = 0; i < 4; i++) {
        const int d0 = r * 8 + 2 * i;
        const int d1 = d0 + 1;
        float s0 = ov[2 * i] + dm[0] * w_sp[d0] + dm[1] * w_sp[64 + d0] + dm[2] * w_sp[128 + d0];
        float s1 = ov[2 * i + 1] + dm[0] * w_sp[d1] + dm[1] * w_sp[64 + d1] + dm[2] * w_sp[128 + d1];
        oh[i] = __floats2half2_rn(s0, s1);
    }
    *(uint4*)(g_ao_h + (size_t)p * ID + rowoff) = ou;
}

// ---------------------------------------------------------------------------
extern "C" void kernel_launch(void* const* d_in, const int* in_sizes, int n_in,
                              void* d_out, int out_size) {
    (void)in_sizes; (void)n_in; (void)out_size;
    const float* xyzs    = (const float*)d_in[0];
    const float* feature = (const float*)d_in[1];
    const float* ln_g    = (const float*)d_in[2];
    const float* ln_b    = (const float*)d_in[3];
    const float* w_qkv   = (const float*)d_in[4];
    const float* w_sp    = (const float*)d_in[5];
    const float* w_out   = (const float*)d_in[6];
    const float* b_out   = (const float*)d_in[7];
    float* out = (float*)d_out;

    void *p_normed, *p_qkv, *p_ao, *p_wqkv, *p_wout;
    cudaGetSymbolAddress(&p_normed, g_normed_h);
    cudaGetSymbolAddress(&p_qkv, g_qkv_h);
    cudaGetSymbolAddress(&p_ao, g_ao_h);
    cudaGetSymbolAddress(&p_wqkv, g_wqkv_h);
    cudaGetSymbolAddress(&p_wout, g_wout_h);
    __half* normed = (__half*)p_normed;
    __half* qkv = (__half*)p_qkv;
    __half* ao = (__half*)p_ao;
    __half* wqkv = (__half*)p_wqkv;
    __half* wout = (__half*)p_wout;

    cudaFuncSetAttribute(ballqkv_kernel, cudaFuncAttributeMaxDynamicSharedMemorySize,
                         GEMM_SMEM);
    cudaFuncSetAttribute(out_gemm_kernel, cudaFuncAttributeMaxDynamicSharedMemorySize,
                         GEMM_SMEM);

    // 1) prep: LN -> fp16 + weight conversions
    prep_kernel<<<PREP_BLOCKS, 256>>>(feature, ln_g, ln_b, w_qkv, w_out);
    // 2) ball query + qkv GEMM (independent; one launch)
    ballqkv_kernel<<<BALL_BLOCKS + QKV_TILES_X * ((BQ * NP) / 128), 256, GEMM_SMEM>>>(
        xyzs, normed, wqkv, qkv);
    // 3) attention + spatial op -> g_ao (fp16)
    attn_kernel<<<(BQ * NP) / 4, 256>>>(xyzs, w_sp);
    // 4) out = gelu(ao @ w_out + b_out) + feature -> fp32
    out_gemm_kernel<<<dim3(DF / 128, (BQ * NP) / 128), 256, GEMM_SMEM>>>(
        ao, wout, out, b_out, feature);
}

// round 15
// speedup vs baseline: 1.1738x; 1.0357x over previous
#include <cuda_runtime.h>
#include <cuda_fp16.h>
#include <math.h>
#include <stdint.h>

// Problem constants
#define BQ   16
#define NP   2048
#define DF   256
#define NH   8
#define DHD  64
#define KN   8
#define ID   512
#define QKV3 1536
#define RAD2 0.09f
#define LNEPS 1e-5f

// Scratch (static device globals; runtime allocation is forbidden)
__device__ int    g_idx[BQ * NP * KN];
__device__ __half g_normed_h[BQ * NP * DF];
__device__ __half g_qkv_h[BQ * NP * QKV3];
__device__ __half g_ao_h[BQ * NP * ID];
__device__ __half g_wqkv_h[DF * QKV3];
__device__ __half g_wout_h[ID * DF];

// ---------------------------------------------------------------------------
// PTX helpers
// ---------------------------------------------------------------------------
__device__ __forceinline__ void mma_f16(float* c, const uint32_t* a, const uint32_t* b) {
    asm volatile(
        "mma.sync.aligned.m16n8k16.row.col.f32.f16.f16.f32 "
        "{%0,%1,%2,%3}, {%4,%5,%6,%7}, {%8,%9}, {%0,%1,%2,%3};"
        : "+f"(c[0]), "+f"(c[1]), "+f"(c[2]), "+f"(c[3])
        : "r"(a[0]), "r"(a[1]), "r"(a[2]), "r"(a[3]), "r"(b[0]), "r"(b[1]));
}
__device__ __forceinline__ void ldsm_x4(uint32_t& r0, uint32_t& r1, uint32_t& r2,
                                        uint32_t& r3, uint32_t addr) {
    asm volatile("ldmatrix.sync.aligned.m8n8.x4.shared.b16 {%0,%1,%2,%3}, [%4];"
                 : "=r"(r0), "=r"(r1), "=r"(r2), "=r"(r3) : "r"(addr));
}
__device__ __forceinline__ void ldsm_x4t(uint32_t& r0, uint32_t& r1, uint32_t& r2,
                                         uint32_t& r3, uint32_t addr) {
    asm volatile("ldmatrix.sync.aligned.m8n8.x4.trans.shared.b16 {%0,%1,%2,%3}, [%4];"
                 : "=r"(r0), "=r"(r1), "=r"(r2), "=r"(r3) : "r"(addr));
}
__device__ __forceinline__ void cp16(uint32_t smem_dst, const void* gsrc) {
    asm volatile("cp.async.cg.shared.global [%0], [%1], 16;" :: "r"(smem_dst), "l"(gsrc));
}
__device__ __forceinline__ void cp_commit() { asm volatile("cp.async.commit_group;"); }
template <int N>
__device__ __forceinline__ void cp_wait() { asm volatile("cp.async.wait_group %0;" :: "n"(N)); }
__device__ __forceinline__ uint32_t smem_u32(const void* p) {
    return (uint32_t)__cvta_generic_to_shared(p);
}

// ---------------------------------------------------------------------------
// Kernel 1 "prep": LN (blocks 0..4095), w_qkv conv (..4479), w_out conv
// (..4607). Zero shared memory. Gamma/beta loaded as float4 (no scalar LDG).
// ---------------------------------------------------------------------------
#define LN_BLOCKS 4096
#define CV1_BLOCKS 384
#define CV2_BLOCKS 128
#define PREP_BLOCKS (LN_BLOCKS + CV1_BLOCKS + CV2_BLOCKS)

__global__ void __launch_bounds__(256) prep_kernel(
    const float* __restrict__ feature, const float* __restrict__ gam,
    const float* __restrict__ bet, const float* __restrict__ w_qkv,
    const float* __restrict__ w_out) {
    const int bid = blockIdx.x;
    const int tid = threadIdx.x;
    if (bid < LN_BLOCKS) {
        const int row = bid * 8 + (tid >> 5);
        const int lane = tid & 31;
        const float* f = feature + (size_t)row * DF + lane * 8;
        float v[8];
        float4 v0 = *(const float4*)f;
        float4 v1 = *(const float4*)(f + 4);
        v[0] = v0.x; v[1] = v0.y; v[2] = v0.z; v[3] = v0.w;
        v[4] = v1.x; v[5] = v1.y; v[6] = v1.z; v[7] = v1.w;
        float s = 0.f;
#pragma unroll
        for (int i = 0; i < 8; i++) s += v[i];
#pragma unroll
        for (int o = 16; o; o >>= 1) s += __shfl_xor_sync(0xffffffffu, s, o);
        const float mu = s * (1.0f / DF);
        float sq = 0.f;
#pragma unroll
        for (int i = 0; i < 8; i++) { float d = v[i] - mu; sq += d * d; }
#pragma unroll
        for (int o = 16; o; o >>= 1) sq += __shfl_xor_sync(0xffffffffu, sq, o);
        const float rs = rsqrtf(sq * (1.0f / DF) + LNEPS);
        // vectorized gamma/beta loads
        float gv[8], bv[8];
        {
            float4 g0 = *(const float4*)(gam + lane * 8);
            float4 g1 = *(const float4*)(gam + lane * 8 + 4);
            float4 c0 = *(const float4*)(bet + lane * 8);
            float4 c1 = *(const float4*)(bet + lane * 8 + 4);
            gv[0] = g0.x; gv[1] = g0.y; gv[2] = g0.z; gv[3] = g0.w;
            gv[4] = g1.x; gv[5] = g1.y; gv[6] = g1.z; gv[7] = g1.w;
            bv[0] = c0.x; bv[1] = c0.y; bv[2] = c0.z; bv[3] = c0.w;
            bv[4] = c1.x; bv[5] = c1.y; bv[6] = c1.z; bv[7] = c1.w;
        }
        __half2 o[4];
#pragma unroll
        for (int i = 0; i < 4; i++) {
            float a = (v[2 * i] - mu) * rs * gv[2 * i] + bv[2 * i];
            float c = (v[2 * i + 1] - mu) * rs * gv[2 * i + 1] + bv[2 * i + 1];
            o[i] = __floats2half2_rn(a, c);
        }
        __half2* op = (__half2*)(g_normed_h + (size_t)row * DF + lane * 8);
#pragma unroll
        for (int i = 0; i < 4; i++) op[i] = o[i];
    } else if (bid < LN_BLOCKS + CV1_BLOCKS) {
        const int i = ((bid - LN_BLOCKS) * 256 + tid) * 4;
        float4 v = *(const float4*)(w_qkv + i);
        __half2* d = (__half2*)(g_wqkv_h + i);
        d[0] = __floats2half2_rn(v.x, v.y);
        d[1] = __floats2half2_rn(v.z, v.w);
    } else {
        const int i = ((bid - LN_BLOCKS - CV1_BLOCKS) * 256 + tid) * 4;
        float4 v = *(const float4*)(w_out + i);
        __half2* d = (__half2*)(g_wout_h + i);
        d[0] = __floats2half2_rn(v.x, v.y);
        d[1] = __floats2half2_rn(v.z, v.w);
    }
}

// ---------------------------------------------------------------------------
// GEMM core: k-tile 32, 4-stage cp.async pipeline, compile-time N/K,
// non-unrolled kt mainloop (L0-I$-resident body).
// ---------------------------------------------------------------------------
#define ASH 40
#define BSH 136
#define STG 4
#define A_STAGE_H (128 * ASH)
#define B_STAGE_H (32 * BSH)
#define GEMM_SMEM ((STG * (A_STAGE_H + B_STAGE_H)) * 2)   /* 75776 B */

template <int EPI, int Nc, int Kc>
__device__ __forceinline__ void gemm_body(
    __half* sh, int brow, int bcol,
    const __half* __restrict__ A, const __half* __restrict__ Bm, void* __restrict__ Cv,
    const float* __restrict__ bias, const float* __restrict__ resid) {
    __half* AsBase = sh;
    __half* BsBase = sh + STG * A_STAGE_H;
    constexpr int KT = Kc / 32;

    const int tid = threadIdx.x;
    const int warp = tid >> 5, lane = tid & 31;
    const int warp_m = warp >> 1, warp_n = warp & 1;

    const int a_r0 = tid >> 2;
    const int a_c = (tid & 3) * 8;
    const int b_r0 = tid >> 4;
    const int b_c = (tid & 15) * 8;

    auto load_tile = [&](int kt, int buf) {
        const uint32_t as_base = smem_u32(AsBase + buf * A_STAGE_H);
        const uint32_t bs_base = smem_u32(BsBase + buf * B_STAGE_H);
#pragma unroll
        for (int i = 0; i < 2; i++) {
            const int row = a_r0 + 64 * i;
            cp16(as_base + (row * ASH + a_c) * 2,
                 A + (size_t)(brow + row) * Kc + kt * 32 + a_c);
        }
#pragma unroll
        for (int i = 0; i < 2; i++) {
            const int row = b_r0 + 16 * i;
            cp16(bs_base + (row * BSH + b_c) * 2,
                 Bm + (size_t)(kt * 32 + row) * Nc + bcol + b_c);
        }
        cp_commit();
    };

    float acc[2][8][4];
#pragma unroll
    for (int mt = 0; mt < 2; mt++)
#pragma unroll
        for (int nt = 0; nt < 8; nt++)
#pragma unroll
            for (int r = 0; r < 4; r++) acc[mt][nt][r] = 0.f;

    load_tile(0, 0);
    load_tile(1, 1);
    load_tile(2, 2);

    const int lg = lane >> 2;
    const int lt = lane & 3;
    const int a_lrow = (lane & 15);
    const int a_lcol = ((lane >> 4) << 3);
    const int b_lk = (lane & 7) + ((lane >> 3) & 1) * 8;
    const int b_ln = ((lane >> 4) << 3);

#pragma unroll 1
    for (int kt = 0; kt < KT; kt++) {
        const int buf = kt & (STG - 1);
        cp_wait<STG - 2>();
        __syncthreads();

        const uint32_t as_u = smem_u32(AsBase + buf * A_STAGE_H);
        const uint32_t bs_u = smem_u32(BsBase + buf * B_STAGE_H);
#pragma unroll
        for (int ks = 0; ks < 2; ks++) {
            uint32_t af[2][4], bf[8][2];
#pragma unroll
            for (int mt = 0; mt < 2; mt++) {
                const int row = warp_m * 32 + mt * 16 + a_lrow;
                const int col = ks * 16 + a_lcol;
                ldsm_x4(af[mt][0], af[mt][1], af[mt][2], af[mt][3],
                        as_u + (row * ASH + col) * 2);
            }
#pragma unroll
            for (int np = 0; np < 4; np++) {
                const int k = ks * 16 + b_lk;
                const int n = warp_n * 64 + np * 16 + b_ln;
                ldsm_x4t(bf[2 * np][0], bf[2 * np][1], bf[2 * np + 1][0], bf[2 * np + 1][1],
                         bs_u + (k * BSH + n) * 2);
            }
#pragma unroll
            for (int mt = 0; mt < 2; mt++)
#pragma unroll
                for (int nt = 0; nt < 8; nt++)
                    mma_f16(acc[mt][nt], af[mt], bf[nt]);
        }

        if (kt + 3 < KT) load_tile(kt + 3, (kt + 3) & (STG - 1));
        else cp_commit();
    }

#pragma unroll
    for (int mt = 0; mt < 2; mt++) {
#pragma unroll
        for (int nt = 0; nt < 8; nt++) {
            const int r = brow + warp_m * 32 + mt * 16 + lg;
            const int c = bcol + warp_n * 64 + nt * 8 + 2 * lt;
#pragma unroll
            for (int h = 0; h < 2; h++) {
                const int rr = r + h * 8;
                float x0 = acc[mt][nt][h * 2 + 0];
                float x1 = acc[mt][nt][h * 2 + 1];
                if (EPI == 0) {
                    __half* C = (__half*)Cv;
                    *(__half2*)(C + (size_t)rr * Nc + c) = __floats2half2_rn(x0, x1);
                } else {
                    float* C = (float*)Cv;
                    const float* rp = resid + (size_t)rr * Nc + c;
                    float a0 = x0 + bias[c];
                    float a1 = x1 + bias[c + 1];
                    float g0 = 0.5f * a0 * (1.0f + erff(a0 * 0.70710678118654752f));
                    float g1 = 0.5f * a1 * (1.0f + erff(a1 * 0.70710678118654752f));
                    float2 o = {g0 + rp[0], g1 + rp[1]};
                    *(float2*)(C + (size_t)rr * Nc + c) = o;
                }
            }
        }
    }
}

// ---------------------------------------------------------------------------
// Kernel: fused ball_query (blocks 0..127) + qkv GEMM (blocks 128..3199).
// ---------------------------------------------------------------------------
#define BALL_BLOCKS 128
#define QKV_TILES_X (QKV3 / 128)   /* 12 */

__global__ void __launch_bounds__(256) ballqkv_kernel(
    const float* __restrict__ xyzs, const __half* __restrict__ A,
    const __half* __restrict__ Bm, __half* __restrict__ C) {
    extern __shared__ char smem_raw[];
    const int tid = threadIdx.x;

    if (blockIdx.x < BALL_BLOCKS) {
        float4* sp = (float4*)smem_raw;
        const int b = blockIdx.x >> 3;
        const int n = ((blockIdx.x & 7) << 8) + tid;
        const float* xb = xyzs + (size_t)b * NP * 3;
        for (int m = tid; m < NP; m += 256) {
            float x = xb[3 * m], y = xb[3 * m + 1], z = xb[3 * m + 2];
            sp[m] = make_float4(x, y, z, x * x + y * y + z * z);
        }
        __syncthreads();
        const float4 q = sp[n];
        int i0 = 0, i1 = 0, i2 = 0, i3 = 0, i4 = 0, i5 = 0, i6 = 0, i7 = 0;
        int cnt = 0;
#pragma unroll 4
        for (int m = 0; m < NP; m++) {
            const float4 c = sp[m];
            const float d2 = q.w + c.w - 2.0f * (q.x * c.x + q.y * c.y + q.z * c.z);
            if (d2 < RAD2 && cnt < KN) {
                if      (cnt == 0) i0 = m;
                else if (cnt == 1) i1 = m;
                else if (cnt == 2) i2 = m;
                else if (cnt == 3) i3 = m;
                else if (cnt == 4) i4 = m;
                else if (cnt == 5) i5 = m;
                else if (cnt == 6) i6 = m;
                else               i7 = m;
                cnt++;
            }
        }
        int* op = g_idx + ((size_t)b * NP + n) * KN;
        op[0] = i0;
        op[1] = (cnt > 1) ? i1 : i0;
        op[2] = (cnt > 2) ? i2 : i0;
        op[3] = (cnt > 3) ? i3 : i0;
        op[4] = (cnt > 4) ? i4 : i0;
        op[5] = (cnt > 5) ? i5 : i0;
        op[6] = (cnt > 6) ? i6 : i0;
        op[7] = (cnt > 7) ? i7 : i0;
        return;
    }

    const int t = blockIdx.x - BALL_BLOCKS;
    const int bcol = (t % QKV_TILES_X) * 128;
    const int brow = (t / QKV_TILES_X) * 128;
    gemm_body<0, QKV3, DF>((__half*)smem_raw, brow, bcol, A, Bm, C, nullptr, nullptr);
}

// ---------------------------------------------------------------------------
// Kernel: out GEMM + bias + exact GELU + residual.
// ---------------------------------------------------------------------------
__global__ void __launch_bounds__(256) out_gemm_kernel(
    const __half* __restrict__ A, const __half* __restrict__ Bm, float* __restrict__ C,
    const float* __restrict__ bias, const float* __restrict__ resid) {
    extern __shared__ char smem_raw[];
    const int bcol = blockIdx.x * 128;
    const int brow = blockIdx.y * 128;
    gemm_body<1, DF, ID>((__half*)smem_raw, brow, bcol, A, Bm, C, bias, resid);
}

// ---------------------------------------------------------------------------
// Kernel: attention v2.1. 8-lane groups; lane owns 8 dims of one head.
// Displacement-max computed in lanes 0..7 via butterfly, then broadcast.
// ---------------------------------------------------------------------------
__global__ void __launch_bounds__(256) attn_kernel(const float* __restrict__ xyzs,
                                                   const float* __restrict__ w_sp) {
    const int warp = threadIdx.x >> 5;
    const int lane = threadIdx.x & 31;
    const int p = blockIdx.x * 4 + (warp >> 1);
    const int b = p >> 11;
    const int head = ((warp & 1) << 2) + (lane >> 3);
    const int r = lane & 7;

    int my_idx = 0;
    float dx = 0.f, dy = 0.f, dz = 0.f;
    if (lane < KN) {
        my_idx = __ldg(&g_idx[(size_t)p * KN + lane]);
        const float* xn = xyzs + ((size_t)b * NP + my_idx) * 3;
        const float* xq = xyzs + (size_t)p * 3;
        dx = xn[0] - xq[0];
        dy = xn[1] - xq[1];
        dz = xn[2] - xq[2];
    }
    int idxs[KN];
#pragma unroll
    for (int j = 0; j < KN; j++) idxs[j] = __shfl_sync(0xffffffffu, my_idx, j);

    const size_t rowoff = (size_t)head * DHD + r * 8;
    uint4 qu = *(const uint4*)(g_qkv_h + (size_t)p * QKV3 + rowoff);
    float2 qf[4];
    {
        const __half2* qh = (const __half2*)&qu;
#pragma unroll
        for (int i = 0; i < 4; i++) qf[i] = __half22float2(qh[i]);
    }

    uint4 ku[KN];
#pragma unroll
    for (int j = 0; j < KN; j++)
        ku[j] = *(const uint4*)(g_qkv_h + ((size_t)b * NP + idxs[j]) * QKV3 + ID + rowoff);
    float logits[KN];
#pragma unroll
    for (int j = 0; j < KN; j++) {
        const __half2* kh = (const __half2*)&ku[j];
        float d = 0.f;
#pragma unroll
        for (int i = 0; i < 4; i++) {
            float2 kf = __half22float2(kh[i]);
            d = fmaf(qf[i].x, kf.x, d);
            d = fmaf(qf[i].y, kf.y, d);
        }
        d += __shfl_xor_sync(0xffffffffu, d, 1);
        d += __shfl_xor_sync(0xffffffffu, d, 2);
        d += __shfl_xor_sync(0xffffffffu, d, 4);
        logits[j] = d * 0.125f;
    }

    float mx = logits[0];
#pragma unroll
    for (int j = 1; j < KN; j++) mx = fmaxf(mx, logits[j]);
    float a[KN];
    float se = 0.f;
#pragma unroll
    for (int j = 0; j < KN; j++) { a[j] = __expf(logits[j] - mx); se += a[j]; }
    const float inv = 1.0f / se;
#pragma unroll
    for (int j = 0; j < KN; j++) a[j] *= inv;

    uint4 vu[KN];
#pragma unroll
    for (int j = 0; j < KN; j++)
        vu[j] = *(const uint4*)(g_qkv_h + ((size_t)b * NP + idxs[j]) * QKV3 + 2 * ID + rowoff);
    float ov[8];
#pragma unroll
    for (int i = 0; i < 8; i++) ov[i] = 0.f;
#pragma unroll
    for (int j = 0; j < KN; j++) {
        const __half2* vh = (const __half2*)&vu[j];
#pragma unroll
        for (int i = 0; i < 4; i++) {
            float2 vf = __half22float2(vh[i]);
            ov[2 * i]     = fmaf(a[j], vf.x, ov[2 * i]);
            ov[2 * i + 1] = fmaf(a[j], vf.y, ov[2 * i + 1]);
        }
    }

    // dm[c] = max_j a[j]*disp_j[c]: lane j (j<8) computes its term (a[] is
    // replicated in every lane), 3-step butterfly max over lanes 0..7, then
    // broadcast from lane 0. Lanes >=8 have garbage during the butterfly but
    // read the final value from lane 0 of their own group-of-8... NOTE: shfl
    // with width 32 from lane 0 gives every lane the correct value.
    float tx, ty, tz;
    {
        // each lane uses its own j = lane (valid only for lane<8)
        float aj = a[lane & 7];
        tx = aj * dx;
        ty = aj * dy;
        tz = aj * dz;
#pragma unroll
        for (int o = 4; o; o >>= 1) {
            tx = fmaxf(tx, __shfl_xor_sync(0xffffffffu, tx, o));
            ty = fmaxf(ty, __shfl_xor_sync(0xffffffffu, ty, o));
            tz = fmaxf(tz, __shfl_xor_sync(0xffffffffu, tz, o));
        }
    }
    float dm[3];
    dm[0] = __shfl_sync(0xffffffffu, tx, 0);
    dm[1] = __shfl_sync(0xffffffffu, ty, 0);
    dm[2] = __shfl_sync(0xffffffffu, tz, 0);

    uint4 ou;
    __half2* oh = (__half2*)&ou;
#pragma unroll
    for (int i = 0; i < 4; i++) {
        const int d0 = r * 8 + 2 * i;
        const int d1 = d0 + 1;
        float s0 = ov[2 * i] + dm[0] * w_sp[d0] + dm[1] * w_sp[64 + d0] + dm[2] * w_sp[128 + d0];
        float s1 = ov[2 * i + 1] + dm[0] * w_sp[d1] + dm[1] * w_sp[64 + d1] + dm[2] * w_sp[128 + d1];
        oh[i] = __floats2half2_rn(s0, s1);
    }
    *(uint4*)(g_ao_h + (size_t)p * ID + rowoff) = ou;
}

// ---------------------------------------------------------------------------
extern "C" void kernel_launch(void* const* d_in, const int* in_sizes, int n_in,
                              void* d_out, int out_size) {
    (void)in_sizes; (void)n_in; (void)out_size;
    const float* xyzs    = (const float*)d_in[0];
    const float* feature = (const float*)d_in[1];
    const float* ln_g    = (const float*)d_in[2];
    const float* ln_b    = (const float*)d_in[3];
    const float* w_qkv   = (const float*)d_in[4];
    const float* w_sp    = (const float*)d_in[5];
    const float* w_out   = (const float*)d_in[6];
    const float* b_out   = (const float*)d_in[7];
    float* out = (float*)d_out;

    void *p_normed, *p_qkv, *p_ao, *p_wqkv, *p_wout;
    cudaGetSymbolAddress(&p_normed, g_normed_h);
    cudaGetSymbolAddress(&p_qkv, g_qkv_h);
    cudaGetSymbolAddress(&p_ao, g_ao_h);
    cudaGetSymbolAddress(&p_wqkv, g_wqkv_h);
    cudaGetSymbolAddress(&p_wout, g_wout_h);
    __half* normed = (__half*)p_normed;
    __half* qkv = (__half*)p_qkv;
    __half* ao = (__half*)p_ao;
    __half* wqkv = (__half*)p_wqkv;
    __half* wout = (__half*)p_wout;

    cudaFuncSetAttribute(ballqkv_kernel, cudaFuncAttributeMaxDynamicSharedMemorySize,
                         GEMM_SMEM);
    cudaFuncSetAttribute(out_gemm_kernel, cudaFuncAttributeMaxDynamicSharedMemorySize,
                         GEMM_SMEM);

    // 1) prep: LN -> fp16 + weight conversions
    prep_kernel<<<PREP_BLOCKS, 256>>>(feature, ln_g, ln_b, w_qkv, w_out);
    // 2) ball query + qkv GEMM (independent; one launch)
    ballqkv_kernel<<<BALL_BLOCKS + QKV_TILES_X * ((BQ * NP) / 128), 256, GEMM_SMEM>>>(
        xyzs, normed, wqkv, qkv);
    // 3) attention + spatial op -> g_ao (fp16)
    attn_kernel<<<(BQ * NP) / 4, 256>>>(xyzs, w_sp);
    // 4) out = gelu(ao @ w_out + b_out) + feature -> fp32
    out_gemm_kernel<<<dim3(DF / 128, (BQ * NP) / 128), 256, GEMM_SMEM>>>(
        ao, wout, out, b_out, feature);
}